// round 2
// baseline (speedup 1.0000x reference)
#include <cuda_runtime.h>

#define B_  2
#define L_  2048
#define E_  512
#define H_  8
#define D_  64
#define NF  33      // rfft bins of length-64 signal
#define NC  65      // real coefficients per row: DC + 32*(cos,sin)
#define BH  (B_*H_)

typedef unsigned long long ull;

// -------- packed f32x2 helpers (Blackwell dual-issue fp32) --------
__device__ __forceinline__ ull splat2(float x) {
    ull r;
    asm("mov.b64 %0, {%1, %1};" : "=l"(r) : "r"(__float_as_uint(x)));
    return r;
}
__device__ __forceinline__ void ffma2(ull& d, ull a, ull b) {
    asm("fma.rn.f32x2 %0, %1, %2, %3;" : "=l"(d) : "l"(a), "l"(b), "l"(d));
}
__device__ __forceinline__ float2 unpack2(ull v) {
    float2 f;
    asm("mov.b64 {%0, %1}, %2;" : "=f"(f.x), "=f"(f.y) : "l"(v));
    return f;
}

// -------- scratch (static device arrays; no allocations) --------
__device__ float g_basis[NC * L_];                 // [k][t]           520 KB
__device__ float g_C[(size_t)BH * L_ * NC];        // [bh][s][k]       8.5 MB
__device__ float g_invZ[BH * L_];                  // [bh][s]
__device__ float g_P[(size_t)BH * L_ * L_];        // [bh][s][t]       268 MB

// ============ K0: basis table  basis[k][t] ============
__global__ void basis_kernel() {
    int idx = blockIdx.x * blockDim.x + threadIdx.x;
    if (idx >= NC * L_) return;
    int t  = idx % L_;
    int kk = idx / L_;
    float v;
    if (kk == 0) {
        v = 1.0f;
    } else {
        int f = (kk + 1) >> 1;
        int r = (f * t) & (L_ - 1);            // exact mod-2048 phase
        float s, c;
        sincospif((float)r * (1.0f / 1024.0f), &s, &c);
        v = (kk & 1) ? c : s;                  // odd kk -> cos, even -> sin
    }
    g_basis[kk * L_ + t] = v;
}

// ============ K1: per-(b,s) 64-pt DFTs -> coeffs, head-mean subtracted ====
__global__ __launch_bounds__(288) void coeff_kernel(const float* __restrict__ q,
                                                    const float* __restrict__ kin) {
    int bs = blockIdx.x;          // b*L + s
    int b  = bs >> 11;
    int s  = bs & (L_ - 1);

    __shared__ float sq[E_], sk[E_];
    __shared__ float twc[64], tws[64];
    __shared__ float A[H_][NC];

    int tid = threadIdx.x;
    for (int i = tid; i < E_; i += blockDim.x) {
        sq[i] = q[(size_t)bs * E_ + i];
        sk[i] = kin[(size_t)bs * E_ + i];
    }
    if (tid < 64) {
        float ss, cc;
        sincospif((float)tid * (1.0f / 32.0f), &ss, &cc);
        twc[tid] = cc; tws[tid] = ss;
    }
    __syncthreads();

    if (tid < H_ * NF) {
        int h = tid / NF, f = tid % NF;
        const float* qh = sq + h * D_;
        const float* kh = sk + h * D_;
        float Qr = 0.f, Qi = 0.f, Kr = 0.f, Ki = 0.f;
#pragma unroll 8
        for (int j = 0; j < 64; j++) {
            int m = (f * j) & 63;
            float c = twc[m], sn = tws[m];
            float qq = qh[j], kk2 = kh[j];
            Qr = fmaf(qq, c, Qr);  Qi = fmaf(-qq, sn, Qi);   // e^{-i th}
            Kr = fmaf(kk2, c, Kr); Ki = fmaf(-kk2, sn, Ki);
        }
        float Xr = Qr * Kr + Qi * Ki;      // Q * conj(K)
        float Xi = Qi * Kr - Qr * Ki;
        if (f == 0) {
            A[h][0] = Xr * (1.0f / 2048.0f);
        } else {
            A[h][2 * f - 1] =  Xr * (1.0f / 1024.0f);   // pairs with cos
            A[h][2 * f]     = -Xi * (1.0f / 1024.0f);   // pairs with sin
        }
    }
    __syncthreads();

    // subtract head mean (exact: corr linear in coeffs), write [bh][s][k]
    for (int idx = tid; idx < H_ * NC; idx += blockDim.x) {
        int h = idx / NC, kk = idx % NC;
        float m = 0.f;
#pragma unroll
        for (int hh = 0; hh < H_; hh++) m += A[hh][kk];
        m *= (1.0f / H_);
        g_C[((size_t)(b * H_ + h) * L_ + s) * NC + kk] = A[h][kk] - m;
    }
}

// ============ K2: corr GEMM (f32x2) + exp -> P, rowsum -> invZ ============
// 128 threads: tx (8) covers 8 t each (64 t), ty (16) covers 4 s each (64 s)
#define TMZ 64
#define TNZ 64
__global__ __launch_bounds__(128) void z_kernel() {
    int bh    = blockIdx.y;
    int sbase = blockIdx.x * TMZ;

    __shared__ float Cs[NC][TMZ + 4];    // [k][s]
    __shared__ float Bs[NC][TNZ];        // [k][t]
    __shared__ float zs[TMZ][9];

    int tid = threadIdx.x;
    int tx  = tid & 7, ty = tid >> 3;

    // transpose-load coefficient tile
    for (int idx = tid; idx < TMZ * NC; idx += 128) {
        int si = idx / NC, kk = idx % NC;
        Cs[kk][si] = g_C[((size_t)bh * L_ + sbase + si) * NC + kk];
    }

    float zpart[4] = {0.f, 0.f, 0.f, 0.f};
    const size_t Pbase = (size_t)bh * L_ * L_;

    for (int tch = 0; tch < L_ / TNZ; tch++) {
        int tbase = tch * TNZ;
        __syncthreads();
        for (int idx = tid; idx < NC * TNZ; idx += 128) {
            int kk = idx / TNZ, tj = idx % TNZ;
            Bs[kk][tj] = g_basis[kk * L_ + tbase + tj];
        }
        __syncthreads();

        ull acc[4][4];
#pragma unroll
        for (int i = 0; i < 4; i++)
#pragma unroll
            for (int j = 0; j < 4; j++) acc[i][j] = 0ull;

#pragma unroll 5
        for (int kk = 0; kk < NC; kk++) {
            float4 a = *(const float4*)&Cs[kk][ty << 2];
            const ull* bp = (const ull*)&Bs[kk][tx << 3];
            ull b0 = bp[0], b1 = bp[1], b2 = bp[2], b3 = bp[3];
            ull a0 = splat2(a.x), a1 = splat2(a.y), a2 = splat2(a.z), a3 = splat2(a.w);
            ffma2(acc[0][0], a0, b0); ffma2(acc[0][1], a0, b1);
            ffma2(acc[0][2], a0, b2); ffma2(acc[0][3], a0, b3);
            ffma2(acc[1][0], a1, b0); ffma2(acc[1][1], a1, b1);
            ffma2(acc[1][2], a1, b2); ffma2(acc[1][3], a1, b3);
            ffma2(acc[2][0], a2, b0); ffma2(acc[2][1], a2, b1);
            ffma2(acc[2][2], a2, b2); ffma2(acc[2][3], a2, b3);
            ffma2(acc[3][0], a3, b0); ffma2(acc[3][1], a3, b1);
            ffma2(acc[3][2], a3, b2); ffma2(acc[3][3], a3, b3);
        }

#pragma unroll
        for (int i = 0; i < 4; i++) {
            float4 w0, w1;
            float2 p0 = unpack2(acc[i][0]);
            float2 p1 = unpack2(acc[i][1]);
            float2 p2 = unpack2(acc[i][2]);
            float2 p3 = unpack2(acc[i][3]);
            w0.x = __expf(p0.x); w0.y = __expf(p0.y);
            w0.z = __expf(p1.x); w0.w = __expf(p1.y);
            w1.x = __expf(p2.x); w1.y = __expf(p2.y);
            w1.z = __expf(p3.x); w1.w = __expf(p3.y);
            zpart[i] += ((w0.x + w0.y) + (w0.z + w0.w)) + ((w1.x + w1.y) + (w1.z + w1.w));
            float* pp = &g_P[Pbase + (size_t)(sbase + (ty << 2) + i) * L_ + tbase + (tx << 3)];
            *(float4*)&pp[0] = w0;
            *(float4*)&pp[4] = w1;
        }
    }

    __syncthreads();
#pragma unroll
    for (int i = 0; i < 4; i++) zs[(ty << 2) + i][tx] = zpart[i];
    __syncthreads();
    if (tid < TMZ) {
        float z = 0.f;
#pragma unroll
        for (int j = 0; j < 8; j++) z += zs[tid][j];
        g_invZ[bh * L_ + sbase + tid] = 1.0f / z;
    }
}

// ============ K3: out (f32x2, pairs over l), scatter ============
// 256 threads: tx (16) covers 4 d each (64 d), ty (16) covers 8 l each (128 l)
#define TL3 128
#define SC3 32
__global__ __launch_bounds__(256) void out_kernel(const float* __restrict__ values,
                                                  float* __restrict__ out) {
    int bh = blockIdx.y;
    int b  = bh >> 3, h = bh & 7;
    int lbase = blockIdx.x * TL3;

    __shared__ float Ws[SC3][TL3];
    __shared__ float Vs[SC3][D_];

    int tid = threadIdx.x;
    int tx  = tid & 15, ty = tid >> 4;

    ull acc[4][4];   // [l-pair][d]
#pragma unroll
    for (int i = 0; i < 4; i++)
#pragma unroll
        for (int j = 0; j < 4; j++) acc[i][j] = 0ull;

    const size_t Pbase = (size_t)bh * L_ * L_;

    for (int sch = 0; sch < L_ / SC3; sch++) {
        int sbase = sch * SC3;
        __syncthreads();
        for (int idx = tid; idx < SC3 * (TL3 / 4); idx += 256) {
            int sc = idx / (TL3 / 4), l4 = idx % (TL3 / 4);
            float4 p = *(const float4*)&g_P[Pbase + (size_t)(sbase + sc) * L_ + lbase + l4 * 4];
            float iz = g_invZ[bh * L_ + sbase + sc];
            p.x *= iz; p.y *= iz; p.z *= iz; p.w *= iz;
            *(float4*)&Ws[sc][l4 * 4] = p;
        }
        for (int idx = tid; idx < SC3 * (D_ / 4); idx += 256) {
            int sc = idx / (D_ / 4), d4 = idx % (D_ / 4);
            *(float4*)&Vs[sc][d4 * 4] =
                *(const float4*)&values[((size_t)(b * L_ + sbase + sc)) * E_ + h * D_ + d4 * 4];
        }
        __syncthreads();

#pragma unroll 8
        for (int sc = 0; sc < SC3; sc++) {
            const ull* wp = (const ull*)&Ws[sc][ty << 3];   // 4 l-pairs
            ull w0 = wp[0], w1 = wp[1], w2 = wp[2], w3 = wp[3];
            float4 bv = *(const float4*)&Vs[sc][tx << 2];
            ull b0 = splat2(bv.x), b1 = splat2(bv.y), b2 = splat2(bv.z), b3 = splat2(bv.w);
            ffma2(acc[0][0], w0, b0); ffma2(acc[0][1], w0, b1);
            ffma2(acc[0][2], w0, b2); ffma2(acc[0][3], w0, b3);
            ffma2(acc[1][0], w1, b0); ffma2(acc[1][1], w1, b1);
            ffma2(acc[1][2], w1, b2); ffma2(acc[1][3], w1, b3);
            ffma2(acc[2][0], w2, b0); ffma2(acc[2][1], w2, b1);
            ffma2(acc[2][2], w2, b2); ffma2(acc[2][3], w2, b3);
            ffma2(acc[3][0], w3, b0); ffma2(acc[3][1], w3, b1);
            ffma2(acc[3][2], w3, b2); ffma2(acc[3][3], w3, b3);
        }
    }

    // faithful reshape of reference: Vt[b,h,dd,l] -> out[b][dd*32+h*4+(l>>9)][l&511]
    int l1     = lbase >> 9;             // constant within tile
    int l0base = lbase & 511;
#pragma unroll
    for (int j = 0; j < 4; j++) {
        int dd  = (tx << 2) + j;
        int row = dd * 32 + h * 4 + l1;
        float* op = out + ((size_t)b * 2048 + row) * 512 + l0base + (ty << 3);
        float2 p0 = unpack2(acc[0][j]);
        float2 p1 = unpack2(acc[1][j]);
        float2 p2 = unpack2(acc[2][j]);
        float2 p3 = unpack2(acc[3][j]);
        float4 w0, w1;
        w0.x = p0.x; w0.y = p0.y; w0.z = p1.x; w0.w = p1.y;
        w1.x = p2.x; w1.y = p2.y; w1.z = p3.x; w1.w = p3.y;
        *(float4*)&op[0] = w0;
        *(float4*)&op[4] = w1;
    }
}

// ============ launch ============
extern "C" void kernel_launch(void* const* d_in, const int* in_sizes, int n_in,
                              void* d_out, int out_size) {
    (void)in_sizes; (void)n_in; (void)out_size;
    const float* q = (const float*)d_in[0];
    const float* k = (const float*)d_in[1];
    const float* v = (const float*)d_in[2];
    float* out = (float*)d_out;

    basis_kernel<<<(NC * L_ + 255) / 256, 256>>>();
    coeff_kernel<<<B_ * L_, 288>>>(q, k);
    z_kernel<<<dim3(L_ / TMZ, BH), 128>>>();
    out_kernel<<<dim3(L_ / TL3, BH), 256>>>(v, out);
}

// round 3
// speedup vs baseline: 1.3611x; 1.3611x over previous
#include <cuda_runtime.h>

#define B_  2
#define L_  2048
#define E_  512
#define H_  8
#define D_  64
#define NF  33      // rfft bins of length-64 signal
#define NC  65      // real coefficients per row: DC + 32*(cos,sin)
#define BH  (B_*H_)

typedef unsigned long long ull;

// -------- packed f32x2 helpers --------
__device__ __forceinline__ ull splat2(float x) {
    ull r;
    asm("mov.b64 %0, {%1, %1};" : "=l"(r) : "r"(__float_as_uint(x)));
    return r;
}
__device__ __forceinline__ void ffma2(ull& d, ull a, ull b) {
    asm("fma.rn.f32x2 %0, %1, %2, %3;" : "=l"(d) : "l"(a), "l"(b), "l"(d));
}
__device__ __forceinline__ float2 unpack2(ull v) {
    float2 f;
    asm("mov.b64 {%0, %1}, %2;" : "=f"(f.x), "=f"(f.y) : "l"(v));
    return f;
}

// -------- scratch --------
__device__ float g_basis[NC * L_];                 // [k][t]
__device__ float g_C[(size_t)BH * L_ * NC];        // [bh][s][k]
__device__ float g_invZ[BH * L_];                  // [bh][s]
__device__ float g_P[(size_t)BH * L_ * L_];        // [bh][s][t]   268 MB

// ============ K0: basis table ============
__global__ void basis_kernel() {
    int idx = blockIdx.x * blockDim.x + threadIdx.x;
    if (idx >= NC * L_) return;
    int t  = idx % L_;
    int kk = idx / L_;
    float v;
    if (kk == 0) {
        v = 1.0f;
    } else {
        int f = (kk + 1) >> 1;
        int r = (f * t) & (L_ - 1);
        float s, c;
        sincospif((float)r * (1.0f / 1024.0f), &s, &c);
        v = (kk & 1) ? c : s;
    }
    g_basis[kk * L_ + t] = v;
}

// ============ K1: per-(b,s) 64-pt DFTs -> coeffs, head-mean subtracted ====
__global__ __launch_bounds__(288) void coeff_kernel(const float* __restrict__ q,
                                                    const float* __restrict__ kin) {
    int bs = blockIdx.x;
    int b  = bs >> 11;
    int s  = bs & (L_ - 1);

    __shared__ float sq[E_], sk[E_];
    __shared__ float twc[64], tws[64];
    __shared__ float A[H_][NC];

    int tid = threadIdx.x;
    for (int i = tid; i < E_; i += blockDim.x) {
        sq[i] = q[(size_t)bs * E_ + i];
        sk[i] = kin[(size_t)bs * E_ + i];
    }
    if (tid < 64) {
        float ss, cc;
        sincospif((float)tid * (1.0f / 32.0f), &ss, &cc);
        twc[tid] = cc; tws[tid] = ss;
    }
    __syncthreads();

    if (tid < H_ * NF) {
        int h = tid / NF, f = tid % NF;
        const float* qh = sq + h * D_;
        const float* kh = sk + h * D_;
        float Qr = 0.f, Qi = 0.f, Kr = 0.f, Ki = 0.f;
#pragma unroll 8
        for (int j = 0; j < 64; j++) {
            int m = (f * j) & 63;
            float c = twc[m], sn = tws[m];
            float qq = qh[j], kk2 = kh[j];
            Qr = fmaf(qq, c, Qr);  Qi = fmaf(-qq, sn, Qi);
            Kr = fmaf(kk2, c, Kr); Ki = fmaf(-kk2, sn, Ki);
        }
        float Xr = Qr * Kr + Qi * Ki;
        float Xi = Qi * Kr - Qr * Ki;
        if (f == 0) {
            A[h][0] = Xr * (1.0f / 2048.0f);
        } else {
            A[h][2 * f - 1] =  Xr * (1.0f / 1024.0f);
            A[h][2 * f]     = -Xi * (1.0f / 1024.0f);
        }
    }
    __syncthreads();

    for (int idx = tid; idx < H_ * NC; idx += blockDim.x) {
        int h = idx / NC, kk = idx % NC;
        float m = 0.f;
#pragma unroll
        for (int hh = 0; hh < H_; hh++) m += A[hh][kk];
        m *= (1.0f / H_);
        g_C[((size_t)(b * H_ + h) * L_ + s) * NC + kk] = A[h][kk] - m;
    }
}

// ============ K2: corr GEMM (f32x2) + exp -> P, rowsum -> invZ ============
// 256 threads: tx(16) owns t-pairs {2tx+32j} j=0..3 (128 t), ty(16) owns 4 s (64 s)
#define TMZ 64
#define TNZ 128
__global__ __launch_bounds__(256) void z_kernel() {
    int bh    = blockIdx.y;
    int sbase = blockIdx.x * TMZ;

    __shared__ float Cs[NC][TMZ + 4];    // [k][s]    17.7 KB
    __shared__ float Bs[NC][TNZ];        // [k][t]    33.3 KB
    __shared__ float zs[TMZ][17];

    int tid = threadIdx.x;
    int tx  = tid & 15, ty = tid >> 4;

    for (int idx = tid; idx < TMZ * NC; idx += 256) {
        int si = idx / NC, kk = idx % NC;
        Cs[kk][si] = g_C[((size_t)bh * L_ + sbase + si) * NC + kk];
    }

    float zpart[4] = {0.f, 0.f, 0.f, 0.f};
    const size_t Pbase = (size_t)bh * L_ * L_;

    for (int tch = 0; tch < L_ / TNZ; tch++) {
        int tbase = tch * TNZ;
        __syncthreads();
        for (int idx = tid; idx < NC * (TNZ / 4); idx += 256) {
            int kk = idx / (TNZ / 4), t4 = idx % (TNZ / 4);
            *(float4*)&Bs[kk][t4 * 4] = *(const float4*)&g_basis[kk * L_ + tbase + t4 * 4];
        }
        __syncthreads();

        ull acc[4][4];
#pragma unroll
        for (int i = 0; i < 4; i++)
#pragma unroll
            for (int j = 0; j < 4; j++) acc[i][j] = 0ull;

#pragma unroll 5
        for (int kk = 0; kk < NC; kk++) {
            float4 a = *(const float4*)&Cs[kk][ty << 2];
            // conflict-free: lanes 0-15 read 128B contiguous per j
            ull b0 = *(const ull*)&Bs[kk][2 * tx];
            ull b1 = *(const ull*)&Bs[kk][2 * tx + 32];
            ull b2 = *(const ull*)&Bs[kk][2 * tx + 64];
            ull b3 = *(const ull*)&Bs[kk][2 * tx + 96];
            ull a0 = splat2(a.x), a1 = splat2(a.y), a2 = splat2(a.z), a3 = splat2(a.w);
            ffma2(acc[0][0], a0, b0); ffma2(acc[0][1], a0, b1);
            ffma2(acc[0][2], a0, b2); ffma2(acc[0][3], a0, b3);
            ffma2(acc[1][0], a1, b0); ffma2(acc[1][1], a1, b1);
            ffma2(acc[1][2], a1, b2); ffma2(acc[1][3], a1, b3);
            ffma2(acc[2][0], a2, b0); ffma2(acc[2][1], a2, b1);
            ffma2(acc[2][2], a2, b2); ffma2(acc[2][3], a2, b3);
            ffma2(acc[3][0], a3, b0); ffma2(acc[3][1], a3, b1);
            ffma2(acc[3][2], a3, b2); ffma2(acc[3][3], a3, b3);
        }

#pragma unroll
        for (int i = 0; i < 4; i++) {
            float* pp = &g_P[Pbase + (size_t)(sbase + (ty << 2) + i) * L_ + tbase];
#pragma unroll
            for (int j = 0; j < 4; j++) {
                float2 p = unpack2(acc[i][j]);
                float2 w;
                w.x = __expf(p.x); w.y = __expf(p.y);
                zpart[i] += w.x + w.y;
                *(float2*)&pp[2 * tx + 32 * j] = w;   // lanes 0-15 contiguous 128B
            }
        }
    }

    __syncthreads();
#pragma unroll
    for (int i = 0; i < 4; i++) zs[(ty << 2) + i][tx] = zpart[i];
    __syncthreads();
    if (tid < TMZ) {
        float z = 0.f;
#pragma unroll
        for (int j = 0; j < 16; j++) z += zs[tid][j];
        g_invZ[bh * L_ + sbase + tid] = 1.0f / z;
    }
}

// ============ K3: out (f32x2 over l-pairs), scatter ============
// 256 threads: tx(16) owns 4 d (64 d), ty(16) owns l-pairs {2ty+32j} j=0,1 (64 l)
#define TL3 64
#define SC3 32
__global__ __launch_bounds__(256) void out_kernel(const float* __restrict__ values,
                                                  float* __restrict__ out) {
    int bh = blockIdx.y;
    int b  = bh >> 3, h = bh & 7;
    int lbase = blockIdx.x * TL3;

    __shared__ float Ws[SC3][TL3];       // 8 KB
    __shared__ float Vs[SC3][D_];        // 8 KB

    int tid = threadIdx.x;
    int tx  = tid & 15, ty = tid >> 4;

    ull acc[2][4];   // [l-pair j][d component]
#pragma unroll
    for (int i = 0; i < 2; i++)
#pragma unroll
        for (int j = 0; j < 4; j++) acc[i][j] = 0ull;

    const size_t Pbase = (size_t)bh * L_ * L_;

    for (int sch = 0; sch < L_ / SC3; sch++) {
        int sbase = sch * SC3;
        __syncthreads();
        for (int idx = tid; idx < SC3 * (TL3 / 4); idx += 256) {
            int sc = idx / (TL3 / 4), l4 = idx % (TL3 / 4);
            float4 p = *(const float4*)&g_P[Pbase + (size_t)(sbase + sc) * L_ + lbase + l4 * 4];
            float iz = g_invZ[bh * L_ + sbase + sc];
            p.x *= iz; p.y *= iz; p.z *= iz; p.w *= iz;
            *(float4*)&Ws[sc][l4 * 4] = p;
        }
        for (int idx = tid; idx < SC3 * (D_ / 4); idx += 256) {
            int sc = idx / (D_ / 4), d4 = idx % (D_ / 4);
            *(float4*)&Vs[sc][d4 * 4] =
                *(const float4*)&values[((size_t)(b * L_ + sbase + sc)) * E_ + h * D_ + d4 * 4];
        }
        __syncthreads();

#pragma unroll 8
        for (int sc = 0; sc < SC3; sc++) {
            ull w0 = *(const ull*)&Ws[sc][2 * ty];         // broadcast per half-warp
            ull w1 = *(const ull*)&Ws[sc][2 * ty + 32];
            float4 bv = *(const float4*)&Vs[sc][tx << 2];
            ull b0 = splat2(bv.x), b1 = splat2(bv.y), b2 = splat2(bv.z), b3 = splat2(bv.w);
            ffma2(acc[0][0], w0, b0); ffma2(acc[0][1], w0, b1);
            ffma2(acc[0][2], w0, b2); ffma2(acc[0][3], w0, b3);
            ffma2(acc[1][0], w1, b0); ffma2(acc[1][1], w1, b1);
            ffma2(acc[1][2], w1, b2); ffma2(acc[1][3], w1, b3);
        }
    }

    // faithful reshape: Vt[b,h,dd,l] -> out[b][dd*32+h*4+(l>>9)][l&511]
    int l1     = lbase >> 9;
    int l0base = lbase & 511;
#pragma unroll
    for (int jd = 0; jd < 4; jd++) {
        int dd  = (tx << 2) + jd;
        int row = dd * 32 + h * 4 + l1;
        float* op = out + ((size_t)b * 2048 + row) * 512 + l0base;
#pragma unroll
        for (int j = 0; j < 2; j++) {
            float2 p = unpack2(acc[j][jd]);
            *(float2*)&op[2 * ty + 32 * j] = p;
        }
    }
}

// ============ launch ============
extern "C" void kernel_launch(void* const* d_in, const int* in_sizes, int n_in,
                              void* d_out, int out_size) {
    (void)in_sizes; (void)n_in; (void)out_size;
    const float* q = (const float*)d_in[0];
    const float* k = (const float*)d_in[1];
    const float* v = (const float*)d_in[2];
    float* out = (float*)d_out;

    basis_kernel<<<(NC * L_ + 255) / 256, 256>>>();
    coeff_kernel<<<B_ * L_, 288>>>(q, k);
    z_kernel<<<dim3(L_ / TMZ, BH), 256>>>();
    out_kernel<<<dim3(L_ / TL3, BH), 256>>>(v, out);
}